// round 5
// baseline (speedup 1.0000x reference)
#include <cuda_runtime.h>
#include <math.h>

#define B_ 4
#define C_ 128
#define H_ 8
#define DH_ 16
#define F_ 4096
#define NR_ 127
#define NS_ 16      // key-split chunks
#define CK_ 256     // keys per chunk
#define SUB_ 8      // sub-chunks per CTA (32 keys each)
#define SMAX_ 64

typedef unsigned long long ull;

// ------------------------- packed f32x2 helpers ----------------------------
__device__ __forceinline__ ull pk2(float lo, float hi) {
    ull r; asm("mov.b64 %0, {%1, %2};" : "=l"(r) : "f"(lo), "f"(hi)); return r;
}
__device__ __forceinline__ void upk2(ull v, float& lo, float& hi) {
    asm("mov.b64 {%0, %1}, %2;" : "=f"(lo), "=f"(hi) : "l"(v));
}
__device__ __forceinline__ ull fma2(ull a, ull b, ull c) {
    ull d; asm("fma.rn.f32x2 %0, %1, %2, %3;" : "=l"(d) : "l"(a), "l"(b), "l"(c)); return d;
}
__device__ __forceinline__ ull add2(ull a, ull b) {
    ull d; asm("add.rn.f32x2 %0, %1, %2;" : "=l"(d) : "l"(a), "l"(b)); return d;
}
__device__ __forceinline__ float ex2(float x) {
    float y; asm("ex2.approx.ftz.f32 %0, %1;" : "=f"(y) : "f"(x)); return y;
}

// ----------------------------- scratch ------------------------------------
__device__ float g_Q[B_*H_*F_*DH_];                 // (b,h,n,d) 8 MB
__device__ float g_K[B_*H_*F_*DH_];
__device__ float g_V[B_*H_*F_*DH_];
__device__ float g_L[2][B_*H_*NS_*SMAX_];
__device__ float g_O[2][B_*H_*NS_*SMAX_*DH_];
__device__ float g_va[B_*C_];                       // Wv0 @ anchor
__device__ float g_k1[B_*H_*DH_];                   // normalized Wk1 @ anchor

// --------------------- prologue: Q/K/V = W @ x -----------------------------
// grid (F/32, 3, B), block 256 = 32 cols x 8 heads
__global__ void proj_kernel(const float* __restrict__ x,
                            const float* __restrict__ Wq,
                            const float* __restrict__ Wk,
                            const float* __restrict__ Wv) {
    __shared__ float WsT[64][132];
    const float* W   = (blockIdx.y == 0) ? Wq  : (blockIdx.y == 1 ? Wk  : Wv);
    float*       out = (blockIdx.y == 0) ? g_Q : (blockIdx.y == 1 ? g_K : g_V);
    const int b  = blockIdx.z;
    const int t  = threadIdx.x;
    const int tx = t & 31;
    const int ty = t >> 5;
    const int n  = blockIdx.x * 32 + tx;

    float acc[16];
#pragma unroll
    for (int i = 0; i < 16; i++) acc[i] = 0.f;

    for (int half = 0; half < 2; half++) {
        __syncthreads();
        for (int idx = t; idx < 64 * 128; idx += 256) {
            int co = idx >> 6, c = idx & 63;
            WsT[c][co] = W[co * 128 + half * 64 + c];
        }
        __syncthreads();
#pragma unroll 4
        for (int c = 0; c < 64; c++) {
            float xv = x[((size_t)(b * 128 + half * 64 + c)) * 4096 + n];
            const float4* wr = (const float4*)&WsT[c][ty * 16];
            float4 w0 = wr[0], w1 = wr[1], w2 = wr[2], w3 = wr[3];
            acc[0]  += w0.x * xv;  acc[1]  += w0.y * xv;
            acc[2]  += w0.z * xv;  acc[3]  += w0.w * xv;
            acc[4]  += w1.x * xv;  acc[5]  += w1.y * xv;
            acc[6]  += w1.z * xv;  acc[7]  += w1.w * xv;
            acc[8]  += w2.x * xv;  acc[9]  += w2.y * xv;
            acc[10] += w2.z * xv;  acc[11] += w2.w * xv;
            acc[12] += w3.x * xv;  acc[13] += w3.y * xv;
            acc[14] += w3.z * xv;  acc[15] += w3.w * xv;
        }
    }
    float4* dst = (float4*)&out[(((size_t)b * 8 + ty) * 4096 + n) * 16];
    dst[0] = make_float4(acc[0],  acc[1],  acc[2],  acc[3]);
    dst[1] = make_float4(acc[4],  acc[5],  acc[6],  acc[7]);
    dst[2] = make_float4(acc[8],  acc[9],  acc[10], acc[11]);
    dst[3] = make_float4(acc[12], acc[13], acc[14], acc[15]);
}

// ----------------- per-ring attention partial + lazy patch -----------------
struct PatchSm {
    float Wk[16][129];
    float Wv[16][129];
    float fc[5][129];
};
struct AttnSm {
    float4 K4[CK_][4];      // 16 KB
    float4 V4[CK_][4];      // 16 KB
    float  q[SMAX_][16];    // 4 KB
};
struct MergeSm {
    float L[SMAX_][SUB_];
    float O[SMAX_][SUB_ * 17 + 1];   // row stride 137 (9t mod 32 distinct)
};
union SmU { PatchSm p; AttnSm a; MergeSm m; };

// grid (NS_, H_, B_), block 256
__global__ void __launch_bounds__(256, 2)
attn_partial(int r,
             const float* __restrict__ x,
             const float* __restrict__ Wk0,
             const float* __restrict__ Wv0,
             float* __restrict__ feats_out) {
    __shared__ SmU sm;
    const int cs = blockIdx.x, h = blockIdx.y, b = blockIdx.z;
    const int t = threadIdx.x;
    const int lo = max(0, r - 63), hi = min(r, 63), s = hi - lo + 1;
    const int par  = r & 1;
    const int par1 = par ^ 1;

    // ---- phase 1: combine ring r-1 partials (plain sums); patch K/V ----
    if (r > 0) {
        const int rm  = r - 1;
        const int lo1 = max(0, rm - 63), hi1 = min(rm, 63);
        int a = cs * 256 - rm;
        int imin = (a <= 0) ? lo1 : (a + 62) / 63;
        if (imin < lo1) imin = lo1;
        int imax = (cs * 256 + 255 - rm) / 63;
        if (imax > hi1) imax = hi1;
        const int np = imax - imin + 1;
        if (np > 0) {
            for (int idx = t; idx < 16 * 128; idx += 256) {
                int row = idx >> 7, c = idx & 127;
                sm.p.Wk[row][c] = Wk0[(h * 16 + row) * 128 + c];
                sm.p.Wv[row][c] = Wv0[(h * 16 + row) * 128 + c];
            }
            for (int idx = t; idx < np * 128; idx += 256) {
                int ci = idx >> 7, c = idx & 127;
                int hh = c >> 4, d = c & 15;
                int i  = imin + ci;
                int qi = i - lo1;
                int col = 63 * i + rm;
                int base = ((b * 8 + hh) * 16) * 64 + qi;
                float L = 0.f, O = 0.f;
#pragma unroll 4
                for (int ch = 0; ch < 16; ch++) {
                    int pidx = base + ch * 64;
                    L += g_L[par1][pidx];
                    O += g_O[par1][(size_t)pidx * 16 + d];
                }
                float f = x[((size_t)(b * 128 + c)) * 4096 + col] + O / L;
                sm.p.fc[ci][c] = f;
                if (h == 0)
                    feats_out[((size_t)(b * 128 + c)) * 4096 + col] = f;
            }
            __syncthreads();
            for (int w = t; w < np * 32; w += 256) {
                int which = w / (np * 16);          // 0->K, 1->V
                int m2 = w % (np * 16);
                int ci = m2 >> 4, row = m2 & 15;
                float accp = 0.f;
                if (which == 0) {
#pragma unroll 8
                    for (int c = 0; c < 128; c++) accp += sm.p.Wk[row][c] * sm.p.fc[ci][c];
                } else {
#pragma unroll 8
                    for (int c = 0; c < 128; c++) accp += sm.p.Wv[row][c] * sm.p.fc[ci][c];
                }
                int col = 63 * (imin + ci) + rm;
                float* dst = which ? g_V : g_K;
                dst[(((size_t)b * 8 + h) * 4096 + col) * 16 + row] = accp;
            }
        }
        __syncthreads();
    }

    // ---- phase 2: stage q, K-chunk, V-chunk into smem ----
    for (int idx = t; idx < s * 16; idx += 256) {
        int i = idx >> 4, d = idx & 15;
        int col = 63 * (lo + i) + r;
        sm.a.q[i][d] = g_Q[(((size_t)b * 8 + h) * 4096 + col) * 16 + d];
    }
    {
        const float4* K4 = (const float4*)&g_K[(((size_t)b * 8 + h) * 4096 + cs * CK_) * 16];
        const float4* V4 = (const float4*)&g_V[(((size_t)b * 8 + h) * 4096 + cs * CK_) * 16];
        float4* Kd = &sm.a.K4[0][0];
        float4* Vd = &sm.a.V4[0][0];
        for (int idx = t; idx < CK_ * 4; idx += 256) { Kd[idx] = K4[idx]; Vd[idx] = V4[idx]; }
    }
    __syncthreads();

    // ---- phase 3: fixed-max softmax partial; 2 queries x 32 keys / thread ----
    const int pair = t & 31;          // warp lanes share sub -> K/V broadcast
    const int sub  = t >> 5;          // 0..7
    const int q0i  = pair * 2;
    const int q1i  = pair * 2 + 1;
    const bool act0 = (q0i < s);
    const bool act1 = (q1i < s);
    const ull Z = 0ull;
    ull oa[8], ob[8];
#pragma unroll
    for (int i = 0; i < 8; i++) { oa[i] = Z; ob[i] = Z; }
    ull l2 = Z;                        // packed (l_q0, l_q1)

    if (act0) {
        const float CSC = 0.36067376022224085f;   // 0.25 * log2(e)
        ull qa[8], qb[8];
#pragma unroll
        for (int i = 0; i < 8; i++) {
            qa[i] = pk2(sm.a.q[q0i][2*i] * CSC, sm.a.q[q0i][2*i+1] * CSC);
            qb[i] = act1 ? pk2(sm.a.q[q1i][2*i] * CSC, sm.a.q[q1i][2*i+1] * CSC) : Z;
        }

        const int j0 = sub * 32;
#pragma unroll 4
        for (int jj = 0; jj < 32; jj++) {
            const int j = j0 + jj;
            const ulonglong2* Kp = (const ulonglong2*)&sm.a.K4[j][0];
            ulonglong2 k01 = Kp[0], k23 = Kp[1], k45 = Kp[2], k67 = Kp[3];

            ull a0 = fma2(qa[0], k01.x, Z);
            ull a1 = fma2(qa[1], k01.y, Z);
            ull b0 = fma2(qb[0], k01.x, Z);
            ull b1 = fma2(qb[1], k01.y, Z);
            a0 = fma2(qa[2], k23.x, a0);  a1 = fma2(qa[3], k23.y, a1);
            b0 = fma2(qb[2], k23.x, b0);  b1 = fma2(qb[3], k23.y, b1);
            a0 = fma2(qa[4], k45.x, a0);  a1 = fma2(qa[5], k45.y, a1);
            b0 = fma2(qb[4], k45.x, b0);  b1 = fma2(qb[5], k45.y, b1);
            a0 = fma2(qa[6], k67.x, a0);  a1 = fma2(qa[7], k67.y, a1);
            b0 = fma2(qb[6], k67.x, b0);  b1 = fma2(qb[7], k67.y, b1);

            ull as = add2(a0, a1);
            ull bs = add2(b0, b1);
            float alo, ahi, blo, bhi;
            upk2(as, alo, ahi);
            upk2(bs, blo, bhi);
            float p0 = ex2(alo + ahi);
            float p1 = ex2(blo + bhi);
            l2 = add2(l2, pk2(p0, p1));
            ull p02 = pk2(p0, p0);
            ull p12 = pk2(p1, p1);

            const ulonglong2* Vp = (const ulonglong2*)&sm.a.V4[j][0];
            ulonglong2 v01 = Vp[0], v23 = Vp[1], v45 = Vp[2], v67 = Vp[3];
            oa[0] = fma2(p02, v01.x, oa[0]);  ob[0] = fma2(p12, v01.x, ob[0]);
            oa[1] = fma2(p02, v01.y, oa[1]);  ob[1] = fma2(p12, v01.y, ob[1]);
            oa[2] = fma2(p02, v23.x, oa[2]);  ob[2] = fma2(p12, v23.x, ob[2]);
            oa[3] = fma2(p02, v23.y, oa[3]);  ob[3] = fma2(p12, v23.y, ob[3]);
            oa[4] = fma2(p02, v45.x, oa[4]);  ob[4] = fma2(p12, v45.x, ob[4]);
            oa[5] = fma2(p02, v45.y, oa[5]);  ob[5] = fma2(p12, v45.y, ob[5]);
            oa[6] = fma2(p02, v67.x, oa[6]);  ob[6] = fma2(p12, v67.x, ob[6]);
            oa[7] = fma2(p02, v67.y, oa[7]);  ob[7] = fma2(p12, v67.y, ob[7]);
        }
    }

    // ---- phase 4: sum the 8 sub-partials per query (smem, aliased) ----
    __syncthreads();                       // everyone done reading K/V
    if (act0) {
        float l0, l1; upk2(l2, l0, l1);
        sm.m.L[q0i][sub] = l0;
#pragma unroll
        for (int i = 0; i < 8; i++) {
            float lo_, hi_; upk2(oa[i], lo_, hi_);
            sm.m.O[q0i][sub * 17 + 2*i]     = lo_;
            sm.m.O[q0i][sub * 17 + 2*i + 1] = hi_;
        }
        if (act1) {
            sm.m.L[q1i][sub] = l1;
#pragma unroll
            for (int i = 0; i < 8; i++) {
                float lo_, hi_; upk2(ob[i], lo_, hi_);
                sm.m.O[q1i][sub * 17 + 2*i]     = lo_;
                sm.m.O[q1i][sub * 17 + 2*i + 1] = hi_;
            }
        }
    }
    __syncthreads();
    if (t < s) {
        float L = 0.f;
        float O[16];
#pragma unroll
        for (int d = 0; d < 16; d++) O[d] = 0.f;
#pragma unroll
        for (int u = 0; u < SUB_; u++) {
            L += sm.m.L[t][u];
#pragma unroll
            for (int d = 0; d < 16; d++)
                O[d] += sm.m.O[t][u * 17 + d];
        }
        int pidx = ((b * 8 + h) * 16 + cs) * 64 + t;
        g_L[par][pidx] = L;
        float4* dst = (float4*)&g_O[par][(size_t)pidx * 16];
        dst[0] = make_float4(O[0],  O[1],  O[2],  O[3]);
        dst[1] = make_float4(O[4],  O[5],  O[6],  O[7]);
        dst[2] = make_float4(O[8],  O[9],  O[10], O[11]);
        dst[3] = make_float4(O[12], O[13], O[14], O[15]);
    }
}

// ---------------- final combine for ring 126 -------------------------------
__global__ void combine_write(int r, const float* __restrict__ x,
                              float* __restrict__ feats_out) {
    const int b = blockIdx.y, qi = blockIdx.x, c = threadIdx.x;
    const int lo = max(0, r - 63);
    const int col = 63 * (lo + qi) + r;
    const int par = r & 1;
    const int hh = c >> 4, d = c & 15;
    int base = ((b * 8 + hh) * 16) * 64 + qi;
    float L = 0.f, O = 0.f;
#pragma unroll 4
    for (int ch = 0; ch < 16; ch++) {
        int pidx = base + ch * 64;
        L += g_L[par][pidx];
        O += g_O[par][(size_t)pidx * 16 + d];
    }
    feats_out[((size_t)(b * 128 + c)) * 4096 + col] =
        x[((size_t)(b * 128 + c)) * 4096 + col] + O / L;
}

// ---------------- epilogue 1 ------------------------------------------------
__global__ void epi1_kernel(const float* __restrict__ Wv0,
                            const float* __restrict__ Wk1,
                            const float* __restrict__ feats_out) {
    __shared__ float anc[128];
    __shared__ float k1raw[128];
    __shared__ float hs[8];
    const int b = blockIdx.x, t = threadIdx.x;
    anc[t] = feats_out[((size_t)(b * 128 + t)) * 4096 + 0];
    __syncthreads();
    float av = 0.f, kv = 0.f;
#pragma unroll 8
    for (int c = 0; c < 128; c++) {
        av += Wv0[t * 128 + c] * anc[c];
        kv += Wk1[t * 128 + c] * anc[c];
    }
    g_va[b * 128 + t] = av;
    k1raw[t] = kv;
    __syncthreads();
    if (t < 8) {
        float ss = 0.f;
#pragma unroll
        for (int d = 0; d < 16; d++) { float v = k1raw[t * 16 + d]; ss += v * v; }
        hs[t] = rsqrtf(ss + 1e-8f);
    }
    __syncthreads();
    g_k1[(b * 8 + (t >> 4)) * 16 + (t & 15)] = k1raw[t] * hs[t >> 4];
}

// ---------------- epilogue 2 ------------------------------------------------
__global__ void epi2_kernel(const float* __restrict__ x,
                            const float* __restrict__ Wq1,
                            float* __restrict__ scores_out) {
    __shared__ float WsT[64][132];
    __shared__ float sva[128];
    __shared__ float sred[8][32];
    const int b  = blockIdx.y;
    const int t  = threadIdx.x;
    const int tx = t & 31;
    const int ty = t >> 5;
    const int n  = blockIdx.x * 32 + tx;

    if (t < 128) sva[t] = g_va[b * 128 + t];

    float acc[16];
#pragma unroll
    for (int i = 0; i < 16; i++) acc[i] = 0.f;

    for (int half = 0; half < 2; half++) {
        __syncthreads();
        for (int idx = t; idx < 64 * 128; idx += 256) {
            int co = idx >> 6, c = idx & 63;
            WsT[c][co] = Wq1[co * 128 + half * 64 + c];
        }
        __syncthreads();
#pragma unroll 4
        for (int c = 0; c < 64; c++) {
            float qx = x[((size_t)(b * 128 + half * 64 + c)) * 4096 + n] + sva[half * 64 + c];
            const float4* wr = (const float4*)&WsT[c][ty * 16];
            float4 w0 = wr[0], w1 = wr[1], w2 = wr[2], w3 = wr[3];
            acc[0]  += w0.x * qx;  acc[1]  += w0.y * qx;
            acc[2]  += w0.z * qx;  acc[3]  += w0.w * qx;
            acc[4]  += w1.x * qx;  acc[5]  += w1.y * qx;
            acc[6]  += w1.z * qx;  acc[7]  += w1.w * qx;
            acc[8]  += w2.x * qx;  acc[9]  += w2.y * qx;
            acc[10] += w2.z * qx;  acc[11] += w2.w * qx;
            acc[12] += w3.x * qx;  acc[13] += w3.y * qx;
            acc[14] += w3.z * qx;  acc[15] += w3.w * qx;
        }
    }
    float qq = 0.f, dot = 0.f;
#pragma unroll
    for (int d = 0; d < 16; d++) {
        qq  += acc[d] * acc[d];
        dot += acc[d] * g_k1[(b * 8 + ty) * 16 + d];
    }
    float m = dot * rsqrtf(qq + 1e-8f);
    sred[ty][tx] = (m + 1.0f) * 0.5f;
    __syncthreads();
    if (ty == 0) {
        float sum = 0.f;
#pragma unroll
        for (int hh = 0; hh < 8; hh++) sum += sred[hh][tx];
        scores_out[(size_t)b * 4096 + n] = sum * 0.125f;
    }
}

// ---------------------------------------------------------------------------
extern "C" void kernel_launch(void* const* d_in, const int* in_sizes, int n_in,
                              void* d_out, int out_size) {
    const float* x   = (const float*)d_in[0];
    const float* Wq0 = (const float*)d_in[1];
    const float* Wk0 = (const float*)d_in[2];
    const float* Wv0 = (const float*)d_in[3];
    const float* Wq1 = (const float*)d_in[4];
    const float* Wk1 = (const float*)d_in[5];
    float* feats_out  = (float*)d_out;
    float* scores_out = feats_out + (size_t)B_ * C_ * F_;

    proj_kernel<<<dim3(128, 3, B_), 256>>>(x, Wq0, Wk0, Wv0);

    for (int r = 0; r < NR_; r++) {
        attn_partial<<<dim3(NS_, H_, B_), 256>>>(r, x, Wk0, Wv0, feats_out);
    }
    combine_write<<<dim3(1, B_), 128>>>(126, x, feats_out);

    epi1_kernel<<<B_, 128>>>(Wv0, Wk1, feats_out);
    epi2_kernel<<<dim3(128, B_), 256>>>(x, Wq1, scores_out);
}